// round 6
// baseline (speedup 1.0000x reference)
#include <cuda_runtime.h>
#include <math.h>

#define NN    50000
#define EE    800000
#define DIN   256
#define DOUTC 256
#define KFIN  512
#define ZMIX  0.8f
#define EPSGN 1e-5f

// ---------------- scratch (static device globals; no allocation) ----------------
__device__ float g_ew[EE];
__device__ float g_deg[NN];
__device__ float g_dinv[NN];
__device__ int   g_cnt[NN];
__device__ int   g_offs[NN + 1];
__device__ int   g_cursor[NN];
__device__ int   g_ccol[EE];
__device__ float g_cw[EE];
__device__ float g_xm[NN * DOUTC];
__device__ float g_agg[NN * DOUTC];
__device__ float g_colsum[DOUTC];
__device__ float g_colsq[DOUTC];
__device__ float g_ns[DOUTC];
__device__ float g_nt[DOUTC];

// Decode a node index that may be stored as int32 OR as float32 bit pattern.
__device__ __forceinline__ int decode_idx(unsigned int w) {
    int v = (w >= 0x3F000000u) ? (int)__uint_as_float(w) : (int)w;
    v = v < 0 ? 0 : (v >= NN ? NN - 1 : v);
    return v;
}

// ---------------- init: zero the accumulators ----------------
__global__ void init_kernel() {
    int i = blockIdx.x * blockDim.x + threadIdx.x;
    int stride = gridDim.x * blockDim.x;
    for (int j = i; j < NN; j += stride) { g_deg[j] = 0.f; g_cnt[j] = 0; }
    for (int j = i; j < DOUTC; j += stride) { g_colsum[j] = 0.f; g_colsq[j] = 0.f; }
}

// ---------------- edge MLP: ew = softplus(relu(ea@Wm1+bm1)@Wm2+bm2); deg/cnt hist ----------------
__global__ __launch_bounds__(256) void edge_mlp_kernel(
    const float* __restrict__ ea, const unsigned int* __restrict__ ei, int estride,
    const float* __restrict__ Wm1, const float* __restrict__ bm1,
    const float* __restrict__ Wm2, const float* __restrict__ bm2)
{
    __shared__ float sW1[16 * 32];
    __shared__ float sB1[32];
    __shared__ float sW2[32];
    __shared__ float sB2;
    int tid = threadIdx.x;
    for (int i = tid; i < 512; i += 256) sW1[i] = Wm1[i];
    if (tid < 32) { sB1[tid] = bm1[tid]; sW2[tid] = Wm2[tid]; }
    if (tid == 0) sB2 = bm2[0];
    __syncthreads();

    int e = blockIdx.x * 256 + tid;
    if (e >= EE) return;

    float a[16];
    const float4* ap = (const float4*)(ea + (size_t)e * 16);
    float4 v0 = ap[0], v1 = ap[1], v2 = ap[2], v3 = ap[3];
    a[0]=v0.x; a[1]=v0.y; a[2]=v0.z; a[3]=v0.w;
    a[4]=v1.x; a[5]=v1.y; a[6]=v1.z; a[7]=v1.w;
    a[8]=v2.x; a[9]=v2.y; a[10]=v2.z; a[11]=v2.w;
    a[12]=v3.x; a[13]=v3.y; a[14]=v3.z; a[15]=v3.w;

    float s = sB2;
    #pragma unroll
    for (int j = 0; j < 32; j++) {
        float h = sB1[j];
        #pragma unroll
        for (int i = 0; i < 16; i++) h = fmaf(a[i], sW1[i * 32 + j], h);
        h = fmaxf(h, 0.f);
        s = fmaf(h, sW2[j], s);
    }
    float ew = (s > 20.f) ? s : log1pf(expf(s));
    g_ew[e] = ew;
    int r = decode_idx(ei[(size_t)estride * e]);
    atomicAdd(&g_deg[r], ew);
    atomicAdd(&g_cnt[r], 1);
}

// ---------------- single-block scan: cnt -> offs/cursor; deg fix -> dinv ----------------
__global__ __launch_bounds__(1024) void scan_kernel() {
    __shared__ int sh[1024];
    __shared__ int carry_s;
    int tid = threadIdx.x;
    if (tid == 0) carry_s = 0;
    __syncthreads();
    for (int base = 0; base < NN; base += 1024) {
        int i = base + tid;
        int v = (i < NN) ? g_cnt[i] : 0;
        sh[tid] = v;
        __syncthreads();
        #pragma unroll
        for (int off = 1; off < 1024; off <<= 1) {
            int t = (tid >= off) ? sh[tid - off] : 0;
            __syncthreads();
            sh[tid] += t;
            __syncthreads();
        }
        int incl = sh[tid];
        int excl = incl - v + carry_s;
        if (i < NN) {
            g_offs[i] = excl;
            g_cursor[i] = excl;
            float d = g_deg[i];
            if (d < 0.5f) d += 1.0f;
            g_dinv[i] = 1.0f / d;
        }
        __syncthreads();
        if (tid == 1023) carry_s += incl;
        __syncthreads();
    }
    if (tid == 0) g_offs[NN] = carry_s;
}

// ---------------- scatter edges into CSR with normalized weights ----------------
__global__ __launch_bounds__(256) void scatter_kernel(const unsigned int* __restrict__ ei, int estride) {
    int e = blockIdx.x * 256 + threadIdx.x;
    if (e >= EE) return;
    int r = decode_idx(ei[(size_t)estride * e]);
    int c = decode_idx(ei[(size_t)estride * (EE + e)]);
    int pos = atomicAdd(&g_cursor[r], 1);
    g_ccol[pos] = c;
    g_cw[pos] = g_ew[e] * g_dinv[r];
}

// ---------------- dual GEMM: C{0,1} = A @ B{0,1} (+bias), epilogue relu+mix or mix ----------------
// !FINAL writes to device-global g_xm via the DEVICE symbol (never pass a
// __device__ array from host code — that decays to the host shadow address
// and on GB300/ATS silently writes host memory). FINAL writes to Out (d_out).
template <bool FINAL>
__global__ __launch_bounds__(256) void dual_gemm_kernel(
    const float* __restrict__ X,      // [M,256] raw x
    const float* __restrict__ B0, const float* __restrict__ B1,  // [K,256]
    const float* __restrict__ b0, const float* __restrict__ b1,  // [256]
    const unsigned int* __restrict__ mask,  // 4-byte; nonzero test works for i32 or f32
    float* __restrict__ Out, int M)
{
    const int K = FINAL ? KFIN : DIN;
    __shared__ float As[16][68];
    __shared__ float Bs0[16][64];
    __shared__ float Bs1[16][64];
    __shared__ float sS[DOUTC];
    __shared__ float sT[DOUTC];

    int tid = threadIdx.x;
    int tx = tid & 15, ty = tid >> 4;
    int m0 = blockIdx.y * 64, n0 = blockIdx.x * 64;

    float* __restrict__ dst = FINAL ? Out : g_xm;

    if (FINAL) {
        sS[tid] = g_ns[tid];
        sT[tid] = g_nt[tid];
        __syncthreads();
    }

    float acc0[4][4]; float acc1[4][4];
    #pragma unroll
    for (int i = 0; i < 4; i++)
        #pragma unroll
        for (int j = 0; j < 4; j++) { acc0[i][j] = 0.f; acc1[i][j] = 0.f; }

    int ar = tid >> 2;          // 0..63  (row within A tile)
    int ac4 = (tid & 3) * 4;    // 0,4,8,12 (k within tile)
    int br = tid >> 4;          // 0..15  (k within B tile)
    int bc4 = (tid & 15) * 4;   // col within B tile

    for (int k0 = 0; k0 < K; k0 += 16) {
        int arow = m0 + ar;
        float4 av = make_float4(0.f, 0.f, 0.f, 0.f);
        if (arow < M) {
            int kk = k0 + ac4;
            if (!FINAL) {
                av = *(const float4*)&X[(size_t)arow * DIN + kk];
            } else if (kk < DOUTC) {
                float4 g = *(const float4*)&g_agg[(size_t)arow * DOUTC + kk];
                av.x = fmaf(sS[kk + 0], g.x, sT[kk + 0]);
                av.y = fmaf(sS[kk + 1], g.y, sT[kk + 1]);
                av.z = fmaf(sS[kk + 2], g.z, sT[kk + 2]);
                av.w = fmaf(sS[kk + 3], g.w, sT[kk + 3]);
            } else {
                av = *(const float4*)&X[(size_t)arow * DIN + (kk - DOUTC)];
            }
        }
        As[ac4 + 0][ar] = av.x;
        As[ac4 + 1][ar] = av.y;
        As[ac4 + 2][ar] = av.z;
        As[ac4 + 3][ar] = av.w;

        *(float4*)&Bs0[br][bc4] = *(const float4*)&B0[(size_t)(k0 + br) * DOUTC + n0 + bc4];
        *(float4*)&Bs1[br][bc4] = *(const float4*)&B1[(size_t)(k0 + br) * DOUTC + n0 + bc4];
        __syncthreads();

        #pragma unroll
        for (int k = 0; k < 16; k++) {
            float4 a = *(const float4*)&As[k][ty * 4];
            float4 p = *(const float4*)&Bs0[k][tx * 4];
            float4 q = *(const float4*)&Bs1[k][tx * 4];
            float av4[4] = {a.x, a.y, a.z, a.w};
            float pv[4] = {p.x, p.y, p.z, p.w};
            float qv[4] = {q.x, q.y, q.z, q.w};
            #pragma unroll
            for (int i = 0; i < 4; i++) {
                #pragma unroll
                for (int j = 0; j < 4; j++) {
                    acc0[i][j] = fmaf(av4[i], pv[j], acc0[i][j]);
                    acc1[i][j] = fmaf(av4[i], qv[j], acc1[i][j]);
                }
            }
        }
        __syncthreads();
    }

    #pragma unroll
    for (int i = 0; i < 4; i++) {
        int row = m0 + ty * 4 + i;
        if (row >= M) continue;
        bool mk = mask[row] != 0u;
        #pragma unroll
        for (int j = 0; j < 4; j++) {
            int cn = n0 + tx * 4 + j;
            float v0 = acc0[i][j] + b0[cn];
            float v1 = acc1[i][j] + b1[cn];
            if (!FINAL) { v0 = fmaxf(v0, 0.f); v1 = fmaxf(v1, 0.f); }
            float res = mk ? (ZMIX * v1 + (1.f - ZMIX) * v0)
                           : (ZMIX * v0 + (1.f - ZMIX) * v1);
            dst[(size_t)row * DOUTC + cn] = res;
        }
    }
}

// ---------------- aggregation: one block (256 thr) per row, gather over CSR ----------------
__global__ __launch_bounds__(256) void agg_kernel() {
    int r = blockIdx.x;
    int d = threadIdx.x;
    int beg = g_offs[r], end = g_offs[r + 1];
    float acc = 0.f;
    for (int j = beg; j < end; j++) {
        int c = g_ccol[j];
        float w = g_cw[j];
        acc = fmaf(w, g_xm[(size_t)c * DOUTC + d], acc);
    }
    g_agg[(size_t)r * DOUTC + d] = acc;
}

// ---------------- column stats: per-channel sum and sumsq over agg ----------------
__global__ __launch_bounds__(256) void colstats_kernel() {
    int d = threadIdx.x;
    float s = 0.f, s2 = 0.f;
    for (int r = blockIdx.x; r < NN; r += gridDim.x) {
        float v = g_agg[(size_t)r * DOUTC + d];
        s += v;
        s2 = fmaf(v, v, s2);
    }
    atomicAdd(&g_colsum[d], s);
    atomicAdd(&g_colsq[d], s2);
}

// ---------------- GraphNorm params: out = ns*agg + nt ----------------
__global__ __launch_bounds__(256) void normparams_kernel(
    const float* __restrict__ gn_w, const float* __restrict__ gn_b,
    const float* __restrict__ gn_alpha)
{
    int d = threadIdx.x;
    float m = g_colsum[d] * (1.0f / NN);
    float a = gn_alpha[d];
    float var = g_colsq[d] * (1.0f / NN) + m * m * (a * a - 2.f * a);
    float rstd = rsqrtf(var + EPSGN);
    float s = gn_w[d] * rstd;
    g_ns[d] = s;
    g_nt[d] = gn_b[d] - s * a * m;
}

// ---------------- launch ----------------
extern "C" void kernel_launch(void* const* d_in, const int* in_sizes, int n_in,
                              void* d_out, int out_size)
{
    const float*        x      = (const float*)d_in[0];
    const unsigned int* ei     = (const unsigned int*)d_in[1];
    // d_in[2] = edge_weight (unused by reference)
    const unsigned int* mask   = (const unsigned int*)d_in[3];
    const float*        ea     = (const float*)d_in[4];
    const float*        Wt0    = (const float*)d_in[5];
    const float*        bt0    = (const float*)d_in[6];
    const float*        Wt1    = (const float*)d_in[7];
    const float*        bt1    = (const float*)d_in[8];
    const float*        Wc0    = (const float*)d_in[9];
    const float*        bc0    = (const float*)d_in[10];
    const float*        Wc1    = (const float*)d_in[11];
    const float*        bc1    = (const float*)d_in[12];
    const float*        gn_w   = (const float*)d_in[13];
    const float*        gn_b   = (const float*)d_in[14];
    const float*        gn_a   = (const float*)d_in[15];
    const float*        Wm1    = (const float*)d_in[16];
    const float*        bm1    = (const float*)d_in[17];
    const float*        Wm2    = (const float*)d_in[18];
    const float*        bm2    = (const float*)d_in[19];
    float*              out    = (float*)d_out;

    // edge_index 32-bit word stride: 1 if stored as 4-byte elems (2*E elems),
    // 2 if the buffer is raw int64 words reported as 4*E int32 elements.
    int estride = (in_sizes[1] >= 4 * EE) ? 2 : 1;

    init_kernel<<<256, 256>>>();
    edge_mlp_kernel<<<(EE + 255) / 256, 256>>>(ea, ei, estride, Wm1, bm1, Wm2, bm2);
    scan_kernel<<<1, 1024>>>();
    scatter_kernel<<<(EE + 255) / 256, 256>>>(ei, estride);

    // xm = mix(mask, relu(x@Wt1+bt1), relu(x@Wt0+bt0)) -> g_xm (device symbol)
    {
        dim3 grid(DOUTC / 64, (NN + 63) / 64);
        dual_gemm_kernel<false><<<grid, 256>>>(x, Wt0, Wt1, bt0, bt1, mask, nullptr, NN);
    }

    agg_kernel<<<NN, 256>>>();
    colstats_kernel<<<512, 256>>>();
    normparams_kernel<<<1, 256>>>(gn_w, gn_b, gn_a);

    // out = mix(mask, xc@Wc1+bc1, xc@Wc0+bc0), xc = [norm(agg) | x]
    {
        dim3 grid(DOUTC / 64, (NN + 63) / 64);
        dual_gemm_kernel<true><<<grid, 256>>>(x, Wc0, Wc1, bc0, bc1, mask, out, NN);
    }
}

// round 10
// speedup vs baseline: 1.7165x; 1.7165x over previous
#include <cuda_runtime.h>
#include <math.h>
#include <cstdint>

#define NN    50000
#define EE    800000
#define DIN   256
#define DOUTC 256
#define ZMIX  0.8f
#define EPSGN 1e-5f

// ---------------- scratch (static device globals; no allocation) ----------------
__device__ float g_ew[EE];
__device__ float g_deg[NN];
__device__ float g_dinv[NN];
__device__ int   g_cnt[NN];
__device__ int   g_offs[NN + 1];
__device__ int   g_cursor[NN];
__device__ int   g_ccol[EE];
__device__ float g_cw[EE];
__device__ float g_xm[NN * DOUTC];
__device__ float g_agg[NN * DOUTC];
__device__ float g_colsum[DOUTC];
__device__ float g_colsq[DOUTC];
__device__ float g_ns[DOUTC];
__device__ float g_nt[DOUTC];

// weights transposed to [n][K] row-major, RNA-rounded to tf32 bit patterns
__device__ float g_Wt0T[256 * 256];
__device__ float g_Wt1T[256 * 256];
__device__ float g_Wc0T[256 * 512];
__device__ float g_Wc1T[256 * 512];

__device__ __forceinline__ float to_tf32(float x) {
    float r;
    asm("cvt.rna.tf32.f32 %0, %1;" : "=f"(r) : "f"(x));
    return r;
}
__device__ __forceinline__ uint32_t fbits(float x) { return __float_as_uint(x); }

#define MMA_TF32(C, A, B0, B1) \
    asm volatile("mma.sync.aligned.m16n8k8.row.col.f32.tf32.tf32.f32 " \
        "{%0,%1,%2,%3}, {%4,%5,%6,%7}, {%8,%9}, {%0,%1,%2,%3};" \
        : "+f"((C)[0]), "+f"((C)[1]), "+f"((C)[2]), "+f"((C)[3]) \
        : "r"((A)[0]), "r"((A)[1]), "r"((A)[2]), "r"((A)[3]), "r"(B0), "r"(B1))

// Decode node index stored as int32 OR float32 bits.
__device__ __forceinline__ int decode_idx(unsigned int w) {
    int v = (w >= 0x3F000000u) ? (int)__uint_as_float(w) : (int)w;
    v = v < 0 ? 0 : (v >= NN ? NN - 1 : v);
    return v;
}

// ---------------- init ----------------
__global__ void init_kernel() {
    int i = blockIdx.x * blockDim.x + threadIdx.x;
    int stride = gridDim.x * blockDim.x;
    for (int j = i; j < NN; j += stride) { g_deg[j] = 0.f; g_cnt[j] = 0; }
    for (int j = i; j < DOUTC; j += stride) { g_colsum[j] = 0.f; g_colsq[j] = 0.f; }
}

// ---------------- weight prep: [K,N] -> [n][K], RNA tf32 ----------------
__global__ __launch_bounds__(256) void prep_weights_kernel(const float* __restrict__ W, int K, int sel) {
    float* dst = (sel == 0) ? g_Wt0T : (sel == 1) ? g_Wt1T : (sel == 2) ? g_Wc0T : g_Wc1T;
    int idx = blockIdx.x * 256 + threadIdx.x;   // over K*64 float4s
    if (idx >= K * 64) return;
    int k = idx >> 6;
    int n4 = idx & 63;
    float4 v = ((const float4*)W)[idx];         // W[k][4*n4 .. 4*n4+3]
    dst[(size_t)(n4 * 4 + 0) * K + k] = to_tf32(v.x);
    dst[(size_t)(n4 * 4 + 1) * K + k] = to_tf32(v.y);
    dst[(size_t)(n4 * 4 + 2) * K + k] = to_tf32(v.z);
    dst[(size_t)(n4 * 4 + 3) * K + k] = to_tf32(v.w);
}

// ---------------- edge MLP ----------------
__global__ __launch_bounds__(256) void edge_mlp_kernel(
    const float* __restrict__ ea, const unsigned int* __restrict__ ei, int estride,
    const float* __restrict__ Wm1, const float* __restrict__ bm1,
    const float* __restrict__ Wm2, const float* __restrict__ bm2)
{
    __shared__ float sW1[16 * 32];
    __shared__ float sB1[32];
    __shared__ float sW2[32];
    __shared__ float sB2;
    int tid = threadIdx.x;
    for (int i = tid; i < 512; i += 256) sW1[i] = Wm1[i];
    if (tid < 32) { sB1[tid] = bm1[tid]; sW2[tid] = Wm2[tid]; }
    if (tid == 0) sB2 = bm2[0];
    __syncthreads();

    int e = blockIdx.x * 256 + tid;
    if (e >= EE) return;

    float a[16];
    const float4* ap = (const float4*)(ea + (size_t)e * 16);
    float4 v0 = ap[0], v1 = ap[1], v2 = ap[2], v3 = ap[3];
    a[0]=v0.x; a[1]=v0.y; a[2]=v0.z; a[3]=v0.w;
    a[4]=v1.x; a[5]=v1.y; a[6]=v1.z; a[7]=v1.w;
    a[8]=v2.x; a[9]=v2.y; a[10]=v2.z; a[11]=v2.w;
    a[12]=v3.x; a[13]=v3.y; a[14]=v3.z; a[15]=v3.w;

    float s = sB2;
    #pragma unroll
    for (int j = 0; j < 32; j++) {
        float h = sB1[j];
        #pragma unroll
        for (int i = 0; i < 16; i++) h = fmaf(a[i], sW1[i * 32 + j], h);
        h = fmaxf(h, 0.f);
        s = fmaf(h, sW2[j], s);
    }
    float ew = (s > 20.f) ? s : log1pf(expf(s));
    g_ew[e] = ew;
    int r = decode_idx(ei[(size_t)estride * e]);
    atomicAdd(&g_deg[r], ew);
    atomicAdd(&g_cnt[r], 1);
}

// ---------------- single-block scan ----------------
__global__ __launch_bounds__(1024) void scan_kernel() {
    __shared__ int sh[1024];
    __shared__ int carry_s;
    int tid = threadIdx.x;
    if (tid == 0) carry_s = 0;
    __syncthreads();
    for (int base = 0; base < NN; base += 1024) {
        int i = base + tid;
        int v = (i < NN) ? g_cnt[i] : 0;
        sh[tid] = v;
        __syncthreads();
        #pragma unroll
        for (int off = 1; off < 1024; off <<= 1) {
            int t = (tid >= off) ? sh[tid - off] : 0;
            __syncthreads();
            sh[tid] += t;
            __syncthreads();
        }
        int incl = sh[tid];
        int excl = incl - v + carry_s;
        if (i < NN) {
            g_offs[i] = excl;
            g_cursor[i] = excl;
            float d = g_deg[i];
            if (d < 0.5f) d += 1.0f;
            g_dinv[i] = 1.0f / d;
        }
        __syncthreads();
        if (tid == 1023) carry_s += incl;
        __syncthreads();
    }
    if (tid == 0) g_offs[NN] = carry_s;
}

// ---------------- scatter into CSR ----------------
__global__ __launch_bounds__(256) void scatter_kernel(const unsigned int* __restrict__ ei, int estride) {
    int e = blockIdx.x * 256 + threadIdx.x;
    if (e >= EE) return;
    int r = decode_idx(ei[(size_t)estride * e]);
    int c = decode_idx(ei[(size_t)estride * (EE + e)]);
    int pos = atomicAdd(&g_cursor[r], 1);
    g_ccol[pos] = c;
    g_cw[pos] = g_ew[e] * g_dinv[r];
}

// ---------------- dual GEMM via mma.sync tf32 ----------------
// CTA: 64 M-rows x 128 N-cols x BOTH branches. grid = (ceil(N/64), 2).
// Warp tile: 64x32 per branch; each lane holds branch0 AND branch1 accs for the
// same (row,col) -> register-local masked mix in the epilogue.
// SMEM rows padded to 20 floats -> conflict-free fragment loads.
#define APITCH 20
#define ABUF   (64 * APITCH)              // 1280 floats
#define BBUF   (256 * APITCH)             // 5120 floats
#define CHBUF  (ABUF + BBUF)              // 6400 floats per stage buffer
#define SMEM_DYN (2 * CHBUF * 4)          // 51200 bytes

template <bool FINAL>
__global__ __launch_bounds__(256, 2) void tc_mma_gemm(
    const float* __restrict__ X,
    const unsigned int* __restrict__ mask,
    const float* __restrict__ bias0, const float* __restrict__ bias1,
    float* __restrict__ Out)
{
    constexpr int K = FINAL ? 512 : 256;
    constexpr int NC = K / 16;
    extern __shared__ float smf[];
    __shared__ float sb0[256], sb1[256], sS[256], sT[256];

    int tid  = threadIdx.x;
    int lane = tid & 31;
    int w    = tid >> 5;
    int wm   = w & 1;          // row half: wm*32
    int wn   = w >> 1;         // col group: wn*32
    int m0   = blockIdx.x * 64;
    int n0   = blockIdx.y * 128;

    sb0[tid] = bias0[tid];
    sb1[tid] = bias1[tid];
    if (FINAL) { sS[tid] = g_ns[tid]; sT[tid] = g_nt[tid]; }
    __syncthreads();

    const float* BT0 = FINAL ? g_Wc0T : g_Wt0T;
    const float* BT1 = FINAL ? g_Wc1T : g_Wt1T;

    float acc[2][2][4][4];     // [branch][mfrag][nfrag][reg]
    #pragma unroll
    for (int b = 0; b < 2; b++)
        #pragma unroll
        for (int f = 0; f < 2; f++)
            #pragma unroll
            for (int g = 0; g < 4; g++)
                #pragma unroll
                for (int r = 0; r < 4; r++) acc[b][f][g][r] = 0.f;

    // ---- prefetch (global -> regs), rounded to tf32 ----
    float4 pa;
    float4 pb[4];
    auto prefetch = [&](int c) {
        // A: 64 rows x 16 k, 1 float4/thread
        {
            int row = tid >> 2, k4 = tid & 3;
            int m = m0 + row;
            int kk = c * 16 + k4 * 4;
            float4 v = make_float4(0.f, 0.f, 0.f, 0.f);
            if (m < NN) {
                if (!FINAL) {
                    v = *(const float4*)&X[(size_t)m * 256 + kk];
                } else if (kk < 256) {
                    float4 g = *(const float4*)&g_agg[(size_t)m * 256 + kk];
                    v.x = fmaf(sS[kk + 0], g.x, sT[kk + 0]);
                    v.y = fmaf(sS[kk + 1], g.y, sT[kk + 1]);
                    v.z = fmaf(sS[kk + 2], g.z, sT[kk + 2]);
                    v.w = fmaf(sS[kk + 3], g.w, sT[kk + 3]);
                } else {
                    v = *(const float4*)&X[(size_t)m * 256 + (kk - 256)];
                }
                v.x = to_tf32(v.x); v.y = to_tf32(v.y);
                v.z = to_tf32(v.z); v.w = to_tf32(v.w);
            }
            pa = v;
        }
        // B: 256 n-rows (2 branches x 128) x 16 k, 4 float4/thread (pre-rounded)
        #pragma unroll
        for (int i = 0; i < 4; i++) {
            int idx = tid + i * 256;
            int row = idx >> 2, k4 = idx & 3;
            int br = row >> 7;
            int nn = (row & 127) + n0;
            const float* src = br ? BT1 : BT0;
            pb[i] = *(const float4*)&src[(size_t)nn * K + c * 16 + k4 * 4];
        }
    };
    auto stores = [&](int buf) {
        float* sA = smf + buf * CHBUF;
        float* sB = sA + ABUF;
        { int row = tid >> 2, k4 = tid & 3; *(float4*)&sA[row * APITCH + k4 * 4] = pa; }
        #pragma unroll
        for (int i = 0; i < 4; i++) {
            int idx = tid + i * 256;
            int row = idx >> 2, k4 = idx & 3;
            *(float4*)&sB[row * APITCH + k4 * 4] = pb[i];
        }
    };
    auto compute = [&](int buf) {
        const float* sA = smf + buf * CHBUF;
        const float* sB = sA + ABUF;
        #pragma unroll
        for (int ks = 0; ks < 16; ks += 8) {
            uint32_t a[2][4];
            #pragma unroll
            for (int f = 0; f < 2; f++) {
                int r = wm * 32 + f * 16 + (lane >> 2);
                int cc = ks + (lane & 3);
                a[f][0] = fbits(sA[r * APITCH + cc]);
                a[f][1] = fbits(sA[(r + 8) * APITCH + cc]);
                a[f][2] = fbits(sA[r * APITCH + cc + 4]);
                a[f][3] = fbits(sA[(r + 8) * APITCH + cc + 4]);
            }
            #pragma unroll
            for (int br = 0; br < 2; br++) {
                #pragma unroll
                for (int g = 0; g < 4; g++) {
                    int n = br * 128 + wn * 32 + g * 8 + (lane >> 2);
                    int kc = ks + (lane & 3);
                    uint32_t b0 = fbits(sB[n * APITCH + kc]);
                    uint32_t b1 = fbits(sB[n * APITCH + kc + 4]);
                    MMA_TF32(acc[br][0][g], a[0], b0, b1);
                    MMA_TF32(acc[br][1][g], a[1], b0, b1);
                }
            }
        }
    };

    prefetch(0);
    stores(0);
    for (int c = 0; c < NC; c++) {
        __syncthreads();
        if (c + 1 < NC) prefetch(c + 1);
        compute(c & 1);
        if (c + 1 < NC) stores((c + 1) & 1);
    }

    // ---- epilogue: bias (+relu) + register-local masked mix ----
    float* dst = FINAL ? Out : g_xm;
    #pragma unroll
    for (int f = 0; f < 2; f++) {
        int r0 = m0 + wm * 32 + f * 16 + (lane >> 2);
        int r1 = r0 + 8;
        unsigned mk0 = (r0 < NN) ? mask[r0] : 0u;
        unsigned mk1 = (r1 < NN) ? mask[r1] : 0u;
        float za0 = mk0 ? (1.f - ZMIX) : ZMIX, zb0 = mk0 ? ZMIX : (1.f - ZMIX);
        float za1 = mk1 ? (1.f - ZMIX) : ZMIX, zb1 = mk1 ? ZMIX : (1.f - ZMIX);
        #pragma unroll
        for (int g = 0; g < 4; g++) {
            int col = n0 + wn * 32 + g * 8 + (lane & 3) * 2;
            float v00 = acc[0][f][g][0] + sb0[col];
            float v01 = acc[0][f][g][1] + sb0[col + 1];
            float v10 = acc[1][f][g][0] + sb1[col];
            float v11 = acc[1][f][g][1] + sb1[col + 1];
            float u00 = acc[0][f][g][2] + sb0[col];
            float u01 = acc[0][f][g][3] + sb0[col + 1];
            float u10 = acc[1][f][g][2] + sb1[col];
            float u11 = acc[1][f][g][3] + sb1[col + 1];
            if (!FINAL) {
                v00 = fmaxf(v00, 0.f); v01 = fmaxf(v01, 0.f);
                v10 = fmaxf(v10, 0.f); v11 = fmaxf(v11, 0.f);
                u00 = fmaxf(u00, 0.f); u01 = fmaxf(u01, 0.f);
                u10 = fmaxf(u10, 0.f); u11 = fmaxf(u11, 0.f);
            }
            if (r0 < NN) {
                float2 o = make_float2(za0 * v00 + zb0 * v10, za0 * v01 + zb0 * v11);
                *(float2*)&dst[(size_t)r0 * 256 + col] = o;
            }
            if (r1 < NN) {
                float2 o = make_float2(za1 * u00 + zb1 * u10, za1 * u01 + zb1 * u11);
                *(float2*)&dst[(size_t)r1 * 256 + col] = o;
            }
        }
    }
}

// ---------------- aggregation: one block per row, gather over CSR ----------------
__global__ __launch_bounds__(256) void agg_kernel() {
    int r = blockIdx.x;
    int d = threadIdx.x;
    int beg = g_offs[r], end = g_offs[r + 1];
    float acc = 0.f;
    for (int j = beg; j < end; j++) {
        int c = g_ccol[j];
        float w = g_cw[j];
        acc = fmaf(w, g_xm[(size_t)c * DOUTC + d], acc);
    }
    g_agg[(size_t)r * DOUTC + d] = acc;
}

// ---------------- column stats ----------------
__global__ __launch_bounds__(256) void colstats_kernel() {
    int d = threadIdx.x;
    float s = 0.f, s2 = 0.f;
    for (int r = blockIdx.x; r < NN; r += gridDim.x) {
        float v = g_agg[(size_t)r * DOUTC + d];
        s += v;
        s2 = fmaf(v, v, s2);
    }
    atomicAdd(&g_colsum[d], s);
    atomicAdd(&g_colsq[d], s2);
}

// ---------------- GraphNorm params ----------------
__global__ __launch_bounds__(256) void normparams_kernel(
    const float* __restrict__ gn_w, const float* __restrict__ gn_b,
    const float* __restrict__ gn_alpha)
{
    int d = threadIdx.x;
    float m = g_colsum[d] * (1.0f / NN);
    float a = gn_alpha[d];
    float var = g_colsq[d] * (1.0f / NN) + m * m * (a * a - 2.f * a);
    float rstd = rsqrtf(var + EPSGN);
    float s = gn_w[d] * rstd;
    g_ns[d] = s;
    g_nt[d] = gn_b[d] - s * a * m;
}

// ---------------- launch ----------------
extern "C" void kernel_launch(void* const* d_in, const int* in_sizes, int n_in,
                              void* d_out, int out_size)
{
    const float*        x      = (const float*)d_in[0];
    const unsigned int* ei     = (const unsigned int*)d_in[1];
    const unsigned int* mask   = (const unsigned int*)d_in[3];
    const float*        ea     = (const float*)d_in[4];
    const float*        Wt0    = (const float*)d_in[5];
    const float*        bt0    = (const float*)d_in[6];
    const float*        Wt1    = (const float*)d_in[7];
    const float*        bt1    = (const float*)d_in[8];
    const float*        Wc0    = (const float*)d_in[9];
    const float*        bc0    = (const float*)d_in[10];
    const float*        Wc1    = (const float*)d_in[11];
    const float*        bc1    = (const float*)d_in[12];
    const float*        gn_w   = (const float*)d_in[13];
    const float*        gn_b   = (const float*)d_in[14];
    const float*        gn_a   = (const float*)d_in[15];
    const float*        Wm1    = (const float*)d_in[16];
    const float*        bm1    = (const float*)d_in[17];
    const float*        Wm2    = (const float*)d_in[18];
    const float*        bm2    = (const float*)d_in[19];
    float*              out    = (float*)d_out;

    int estride = (in_sizes[1] >= 4 * EE) ? 2 : 1;

    cudaFuncSetAttribute(tc_mma_gemm<false>,
                         cudaFuncAttributeMaxDynamicSharedMemorySize, SMEM_DYN);
    cudaFuncSetAttribute(tc_mma_gemm<true>,
                         cudaFuncAttributeMaxDynamicSharedMemorySize, SMEM_DYN);

    init_kernel<<<256, 256>>>();
    prep_weights_kernel<<<64, 256>>>(Wt0, 256, 0);
    prep_weights_kernel<<<64, 256>>>(Wt1, 256, 1);
    prep_weights_kernel<<<128, 256>>>(Wc0, 512, 2);
    prep_weights_kernel<<<128, 256>>>(Wc1, 512, 3);
    edge_mlp_kernel<<<(EE + 255) / 256, 256>>>(ea, ei, estride, Wm1, bm1, Wm2, bm2);
    scan_kernel<<<1, 1024>>>();
    scatter_kernel<<<(EE + 255) / 256, 256>>>(ei, estride);

    dim3 ggrid((NN + 63) / 64, 2);
    // xm = mix(mask, relu(x@Wt1+bt1), relu(x@Wt0+bt0)) -> g_xm
    tc_mma_gemm<false><<<ggrid, 256, SMEM_DYN>>>(x, mask, bt0, bt1, nullptr);

    agg_kernel<<<NN, 256>>>();
    colstats_kernel<<<512, 256>>>();
    normparams_kernel<<<1, 256>>>(gn_w, gn_b, gn_a);

    // out = mix(mask, xc@Wc1+bc1, xc@Wc0+bc0), xc = [norm(agg) | x]
    tc_mma_gemm<true><<<ggrid, 256, SMEM_DYN>>>(x, mask, bc0, bc1, out);
}

// round 13
// speedup vs baseline: 1.9352x; 1.1274x over previous
#include <cuda_runtime.h>
#include <math.h>
#include <cstdint>

#define NN    50000
#define EE    800000
#define DIN   256
#define DOUTC 256
#define ZMIX  0.8f
#define EPSGN 1e-5f

// ---------------- scratch (static device globals; no allocation) ----------------
__device__ float g_ew[EE];
__device__ float g_deg[NN];
__device__ float g_dinv[NN];
__device__ int   g_cnt[NN];
__device__ int   g_offs[NN + 1];
__device__ int   g_cursor[NN];
__device__ int   g_ccol[EE];
__device__ float g_cw[EE];
__device__ float g_xm[NN * DOUTC];
__device__ float g_agg[NN * DOUTC];
__device__ float g_colsum[DOUTC];
__device__ float g_colsq[DOUTC];
__device__ float g_ns[DOUTC];
__device__ float g_nt[DOUTC];
__device__ int   g_bsum[64];
__device__ int   g_boff[64];

// weights: [n][K], RNA-rounded tf32, with each 16-k chunk permuted so that
// word (c*4+q) holds W[k_local = c + 4q][n]  (c=0..3, q=0..3).
// => compute-side B fragment (both k-halves) is ONE LDS.128 at offset (lane&3)*4.
__device__ float g_Wt0T[256 * 256];
__device__ float g_Wt1T[256 * 256];
__device__ float g_Wc0T[256 * 512];
__device__ float g_Wc1T[256 * 512];

__device__ __forceinline__ float to_tf32(float x) {
    float r;
    asm("cvt.rna.tf32.f32 %0, %1;" : "=f"(r) : "f"(x));
    return r;
}
__device__ __forceinline__ uint32_t fbits(float x) { return __float_as_uint(x); }

#define MMA_TF32(C, A, B0, B1) \
    asm volatile("mma.sync.aligned.m16n8k8.row.col.f32.tf32.tf32.f32 " \
        "{%0,%1,%2,%3}, {%4,%5,%6,%7}, {%8,%9}, {%0,%1,%2,%3};" \
        : "+f"((C)[0]), "+f"((C)[1]), "+f"((C)[2]), "+f"((C)[3]) \
        : "r"((A)[0]), "r"((A)[1]), "r"((A)[2]), "r"((A)[3]), "r"(B0), "r"(B1))

__device__ __forceinline__ int decode_idx(unsigned int w) {
    int v = (w >= 0x3F000000u) ? (int)__uint_as_float(w) : (int)w;
    v = v < 0 ? 0 : (v >= NN ? NN - 1 : v);
    return v;
}

// ---------------- init ----------------
__global__ void init_kernel() {
    int i = blockIdx.x * blockDim.x + threadIdx.x;
    int stride = gridDim.x * blockDim.x;
    for (int j = i; j < NN; j += stride) { g_deg[j] = 0.f; g_cnt[j] = 0; }
    for (int j = i; j < DOUTC; j += stride) { g_colsum[j] = 0.f; g_colsq[j] = 0.f; }
}

// ---------------- weight prep: [K,N] -> [n][K] permuted-chunk, RNA tf32 ----------------
__global__ __launch_bounds__(256) void prep_weights_kernel(const float* __restrict__ W, int K, int sel) {
    float* dst = (sel == 0) ? g_Wt0T : (sel == 1) ? g_Wt1T : (sel == 2) ? g_Wc0T : g_Wc1T;
    int idx = blockIdx.x * 256 + threadIdx.x;   // over K*64 float4s
    if (idx >= K * 64) return;
    int k = idx >> 6;
    int n4 = idx & 63;
    float4 v = ((const float4*)W)[idx];         // W[k][4*n4 .. 4*n4+3]
    int kl = k & 15;
    int off = (k >> 4) * 16 + (kl & 3) * 4 + (kl >> 2);
    float vv[4] = {v.x, v.y, v.z, v.w};
    #pragma unroll
    for (int j = 0; j < 4; j++)
        dst[(size_t)(n4 * 4 + j) * K + off] = to_tf32(vv[j]);
}

// ---------------- edge MLP ----------------
__global__ __launch_bounds__(256) void edge_mlp_kernel(
    const float* __restrict__ ea, const unsigned int* __restrict__ ei, int estride,
    const float* __restrict__ Wm1, const float* __restrict__ bm1,
    const float* __restrict__ Wm2, const float* __restrict__ bm2)
{
    __shared__ float sW1[16 * 32];
    __shared__ float sB1[32];
    __shared__ float sW2[32];
    __shared__ float sB2;
    int tid = threadIdx.x;
    for (int i = tid; i < 512; i += 256) sW1[i] = Wm1[i];
    if (tid < 32) { sB1[tid] = bm1[tid]; sW2[tid] = Wm2[tid]; }
    if (tid == 0) sB2 = bm2[0];
    __syncthreads();

    int e = blockIdx.x * 256 + tid;
    if (e >= EE) return;

    float a[16];
    const float4* ap = (const float4*)(ea + (size_t)e * 16);
    float4 v0 = ap[0], v1 = ap[1], v2 = ap[2], v3 = ap[3];
    a[0]=v0.x; a[1]=v0.y; a[2]=v0.z; a[3]=v0.w;
    a[4]=v1.x; a[5]=v1.y; a[6]=v1.z; a[7]=v1.w;
    a[8]=v2.x; a[9]=v2.y; a[10]=v2.z; a[11]=v2.w;
    a[12]=v3.x; a[13]=v3.y; a[14]=v3.z; a[15]=v3.w;

    float s = sB2;
    #pragma unroll
    for (int j = 0; j < 32; j++) {
        float h = sB1[j];
        #pragma unroll
        for (int i = 0; i < 16; i++) h = fmaf(a[i], sW1[i * 32 + j], h);
        h = fmaxf(h, 0.f);
        s = fmaf(h, sW2[j], s);
    }
    float ew = (s > 20.f) ? s : log1pf(expf(s));
    g_ew[e] = ew;
    int r = decode_idx(ei[(size_t)estride * e]);
    atomicAdd(&g_deg[r], ew);
    atomicAdd(&g_cnt[r], 1);
}

// ---------------- parallel scan: reduce -> spine -> downsweep ----------------
#define SCAN_NB ((NN + 1023) / 1024)

__global__ __launch_bounds__(1024) void scan_reduce_kernel() {
    __shared__ int sw[32];
    int b = blockIdx.x, tid = threadIdx.x;
    int i = b * 1024 + tid;
    int s = (i < NN) ? g_cnt[i] : 0;
    #pragma unroll
    for (int o = 16; o; o >>= 1) s += __shfl_down_sync(~0u, s, o);
    if ((tid & 31) == 0) sw[tid >> 5] = s;
    __syncthreads();
    if (tid < 32) {
        int t = sw[tid];
        #pragma unroll
        for (int o = 16; o; o >>= 1) t += __shfl_down_sync(~0u, t, o);
        if (tid == 0) g_bsum[b] = t;
    }
}

__global__ __launch_bounds__(64) void scan_spine_kernel() {
    __shared__ int sh[64];
    int tid = threadIdx.x;
    int v = (tid < SCAN_NB) ? g_bsum[tid] : 0;
    sh[tid] = v;
    __syncthreads();
    #pragma unroll
    for (int o = 1; o < 64; o <<= 1) {
        int t = (tid >= o) ? sh[tid - o] : 0;
        __syncthreads();
        sh[tid] += t;
        __syncthreads();
    }
    if (tid < SCAN_NB) g_boff[tid] = sh[tid] - v;
    if (tid == 0) g_offs[NN] = sh[SCAN_NB - 1];
}

__global__ __launch_bounds__(1024) void scan_final_kernel() {
    __shared__ int wsum[32];
    int b = blockIdx.x, tid = threadIdx.x;
    int lane = tid & 31, wd = tid >> 5;
    int i = b * 1024 + tid;
    int v = (i < NN) ? g_cnt[i] : 0;
    int incl = v;
    #pragma unroll
    for (int o = 1; o < 32; o <<= 1) {
        int t = __shfl_up_sync(~0u, incl, o);
        if (lane >= o) incl += t;
    }
    if (lane == 31) wsum[wd] = incl;
    __syncthreads();
    if (tid < 32) {
        int t = wsum[tid];
        int inc = t;
        #pragma unroll
        for (int o = 1; o < 32; o <<= 1) {
            int u = __shfl_up_sync(~0u, inc, o);
            if (tid >= o) inc += u;
        }
        wsum[tid] = inc - t;
    }
    __syncthreads();
    if (i < NN) {
        int excl = incl - v + wsum[wd] + g_boff[b];
        g_offs[i] = excl;
        g_cursor[i] = excl;
        float d = g_deg[i];
        if (d < 0.5f) d += 1.0f;
        g_dinv[i] = 1.0f / d;
    }
}

// ---------------- scatter into CSR ----------------
__global__ __launch_bounds__(256) void scatter_kernel(const unsigned int* __restrict__ ei, int estride) {
    int e = blockIdx.x * 256 + threadIdx.x;
    if (e >= EE) return;
    int r = decode_idx(ei[(size_t)estride * e]);
    int c = decode_idx(ei[(size_t)estride * (EE + e)]);
    int pos = atomicAdd(&g_cursor[r], 1);
    g_ccol[pos] = c;
    g_cw[pos] = g_ew[e] * g_dinv[r];
}

// ---------------- dual GEMM via mma.sync tf32, fragment-packed smem ----------------
// CTA: 64 M x 128 N x both branches; grid (782, 2); warp tile 64x32 per branch.
// A packed per chunk:  [ks(2)][frag(4)][lane(32)][reg(4)]  = 1024 floats (4 KB)
// B packed per chunk:  [n(256)][16]  with permuted word order = 4096 floats (16 KB)
#define A_PK  1024
#define B_PK  4096
#define CHBUF (A_PK + B_PK)
#define SMEM_DYN (2 * CHBUF * 4)    // 40960 bytes

template <bool FINAL>
__global__ __launch_bounds__(256, 2) void tc_mma_gemm(
    const float* __restrict__ X,
    const unsigned int* __restrict__ mask,
    const float* __restrict__ bias0, const float* __restrict__ bias1,
    float* __restrict__ Out)
{
    constexpr int K = FINAL ? 512 : 256;
    constexpr int NC = K / 16;
    extern __shared__ float smf[];
    __shared__ float sb0[256], sb1[256], sS[256], sT[256];

    int tid  = threadIdx.x;
    int lane = tid & 31;
    int w    = tid >> 5;
    int wm   = w & 1;          // row half: wm*32
    int wn   = w >> 1;         // col group: wn*32
    int m0   = blockIdx.x * 64;
    int n0   = blockIdx.y * 128;

    sb0[tid] = bias0[tid];
    sb1[tid] = bias1[tid];
    if (FINAL) { sS[tid] = g_ns[tid]; sT[tid] = g_nt[tid]; }
    __syncthreads();

    const float* BT0 = FINAL ? g_Wc0T : g_Wt0T;
    const float* BT1 = FINAL ? g_Wc1T : g_Wt1T;

    float acc[2][2][4][4];     // [branch][mfrag][nfrag][reg]
    #pragma unroll
    for (int b = 0; b < 2; b++)
        #pragma unroll
        for (int f = 0; f < 2; f++)
            #pragma unroll
            for (int g = 0; g < 4; g++)
                #pragma unroll
                for (int r = 0; r < 4; r++) acc[b][f][g][r] = 0.f;

    // staging decomposition (fixed per thread)
    const int arow = tid >> 2;            // 0..63
    const int ak4  = tid & 3;             // float4 index in k (0..3)
    const int arr  = arow & 15;
    const int afr  = arow >> 4;
    // A scatter targets: reg constant per thread, 4 consecutive lane slots
    const int aks   = ak4 >> 1;
    const int areg  = ((arr >= 8) ? 1 : 0) + ((ak4 & 1) ? 2 : 0);
    const int abase = ((aks * 4 + afr) * 32 + (arr & 7) * 4) * 4 + areg;

    float4 pa;
    float4 pb[4];
    auto prefetch = [&](int c) {
        // A: 64 rows x 16 k, 1 float4/thread (tf32-rounded, GraphNorm fused if FINAL)
        {
            int m = m0 + arow;
            int kk = c * 16 + ak4 * 4;
            float4 v = make_float4(0.f, 0.f, 0.f, 0.f);
            if (m < NN) {
                if (!FINAL) {
                    v = *(const float4*)&X[(size_t)m * 256 + kk];
                } else if (kk < 256) {
                    float4 g = *(const float4*)&g_agg[(size_t)m * 256 + kk];
                    v.x = fmaf(sS[kk + 0], g.x, sT[kk + 0]);
                    v.y = fmaf(sS[kk + 1], g.y, sT[kk + 1]);
                    v.z = fmaf(sS[kk + 2], g.z, sT[kk + 2]);
                    v.w = fmaf(sS[kk + 3], g.w, sT[kk + 3]);
                } else {
                    v = *(const float4*)&X[(size_t)m * 256 + (kk - 256)];
                }
                v.x = to_tf32(v.x); v.y = to_tf32(v.y);
                v.z = to_tf32(v.z); v.w = to_tf32(v.w);
            }
            pa = v;
        }
        // B: straight float4 copy of permuted weights (256 n-rows x 4 quads)
        #pragma unroll
        for (int i = 0; i < 4; i++) {
            int idx = tid + i * 256;
            int nr = idx >> 2, j4 = idx & 3;
            int br = nr >> 7;
            int nn = (nr & 127) + n0;
            const float* src = br ? BT1 : BT0;
            pb[i] = *(const float4*)&src[(size_t)nn * K + c * 16 + j4 * 4];
        }
    };
    auto stores = [&](int buf) {
        float* sA = smf + buf * CHBUF;
        float* sB = sA + A_PK;
        // A scatter: 4 scalar stores, stride 16B, same reg slot
        sA[abase + 0]  = pa.x;
        sA[abase + 4]  = pa.y;
        sA[abase + 8]  = pa.z;
        sA[abase + 12] = pa.w;
        #pragma unroll
        for (int i = 0; i < 4; i++) {
            int idx = tid + i * 256;
            int nr = idx >> 2, j4 = idx & 3;
            *(float4*)&sB[nr * 16 + j4 * 4] = pb[i];
        }
    };
    auto compute = [&](int buf) {
        const float* sA = smf + buf * CHBUF;
        const float* sB = sA + A_PK;
        // A fragments: one LDS.128 each
        uint32_t a[2][2][4];   // [ks][mfrag][reg]
        #pragma unroll
        for (int ks = 0; ks < 2; ks++)
            #pragma unroll
            for (int f = 0; f < 2; f++) {
                float4 av = *(const float4*)&sA[((ks * 4 + (wm * 2 + f)) * 32 + lane) * 4];
                a[ks][f][0] = fbits(av.x); a[ks][f][1] = fbits(av.y);
                a[ks][f][2] = fbits(av.z); a[ks][f][3] = fbits(av.w);
            }
        #pragma unroll
        for (int br = 0; br < 2; br++) {
            #pragma unroll
            for (int g = 0; g < 4; g++) {
                int n = br * 128 + wn * 32 + g * 8 + (lane >> 2);
                float4 bb = *(const float4*)&sB[n * 16 + (lane & 3) * 4];
                uint32_t b00 = fbits(bb.x), b01 = fbits(bb.y);
                uint32_t b10 = fbits(bb.z), b11 = fbits(bb.w);
                MMA_TF32(acc[br][0][g], a[0][0], b00, b01);
                MMA_TF32(acc[br][1][g], a[0][1], b00, b01);
                MMA_TF32(acc[br][0][g], a[1][0], b10, b11);
                MMA_TF32(acc[br][1][g], a[1][1], b10, b11);
            }
        }
    };

    prefetch(0);
    stores(0);
    for (int c = 0; c < NC; c++) {
        __syncthreads();
        if (c + 1 < NC) prefetch(c + 1);
        compute(c & 1);
        if (c + 1 < NC) stores((c + 1) & 1);
    }

    // ---- epilogue: bias (+relu) + register-local masked mix ----
    float* dst = FINAL ? Out : g_xm;
    #pragma unroll
    for (int f = 0; f < 2; f++) {
        int r0 = m0 + wm * 32 + f * 16 + (lane >> 2);
        int r1 = r0 + 8;
        unsigned mk0 = (r0 < NN) ? mask[r0] : 0u;
        unsigned mk1 = (r1 < NN) ? mask[r1] : 0u;
        float za0 = mk0 ? (1.f - ZMIX) : ZMIX, zb0 = mk0 ? ZMIX : (1.f - ZMIX);
        float za1 = mk1 ? (1.f - ZMIX) : ZMIX, zb1 = mk1 ? ZMIX : (1.f - ZMIX);
        #pragma unroll
        for (int g = 0; g < 4; g++) {
            int col = n0 + wn * 32 + g * 8 + (lane & 3) * 2;
            float v00 = acc[0][f][g][0] + sb0[col];
            float v01 = acc[0][f][g][1] + sb0[col + 1];
            float v10 = acc[1][f][g][0] + sb1[col];
            float v11 = acc[1][f][g][1] + sb1[col + 1];
            float u00 = acc[0][f][g][2] + sb0[col];
            float u01 = acc[0][f][g][3] + sb0[col + 1];
            float u10 = acc[1][f][g][2] + sb1[col];
            float u11 = acc[1][f][g][3] + sb1[col + 1];
            if (!FINAL) {
                v00 = fmaxf(v00, 0.f); v01 = fmaxf(v01, 0.f);
                v10 = fmaxf(v10, 0.f); v11 = fmaxf(v11, 0.f);
                u00 = fmaxf(u00, 0.f); u01 = fmaxf(u01, 0.f);
                u10 = fmaxf(u10, 0.f); u11 = fmaxf(u11, 0.f);
            }
            if (r0 < NN) {
                float2 o = make_float2(za0 * v00 + zb0 * v10, za0 * v01 + zb0 * v11);
                *(float2*)&dst[(size_t)r0 * 256 + col] = o;
            }
            if (r1 < NN) {
                float2 o = make_float2(za1 * u00 + zb1 * u10, za1 * u01 + zb1 * u11);
                *(float2*)&dst[(size_t)r1 * 256 + col] = o;
            }
        }
    }
}

// ---------------- aggregation: one block per row, gather over CSR ----------------
__global__ __launch_bounds__(256) void agg_kernel() {
    int r = blockIdx.x;
    int d = threadIdx.x;
    int beg = g_offs[r], end = g_offs[r + 1];
    float acc = 0.f;
    for (int j = beg; j < end; j++) {
        int c = g_ccol[j];
        float w = g_cw[j];
        acc = fmaf(w, g_xm[(size_t)c * DOUTC + d], acc);
    }
    g_agg[(size_t)r * DOUTC + d] = acc;
}

// ---------------- column stats ----------------
__global__ __launch_bounds__(256) void colstats_kernel() {
    int d = threadIdx.x;
    float s = 0.f, s2 = 0.f;
    for (int r = blockIdx.x; r < NN; r += gridDim.x) {
        float v = g_agg[(size_t)r * DOUTC + d];
        s += v;
        s2 = fmaf(v, v, s2);
    }
    atomicAdd(&g_colsum[d], s);
    atomicAdd(&g_colsq[d], s2);
}

// ---------------- GraphNorm params ----------------
__global__ __launch_bounds__(256) void normparams_kernel(
    const float* __restrict__ gn_w, const float* __restrict__ gn_b,
    const float* __restrict__ gn_alpha)
{
    int d = threadIdx.x;
    float m = g_colsum[d] * (1.0f / NN);
    float a = gn_alpha[d];
    float var = g_colsq[d] * (1.0f / NN) + m * m * (a * a - 2.f * a);
    float rstd = rsqrtf(var + EPSGN);
    float s = gn_w[d] * rstd;
    g_ns[d] = s;
    g_nt[d] = gn_b[d] - s * a * m;
}

// ---------------- launch ----------------
extern "C" void kernel_launch(void* const* d_in, const int* in_sizes, int n_in,
                              void* d_out, int out_size)
{
    const float*        x      = (const float*)d_in[0];
    const unsigned int* ei     = (const unsigned int*)d_in[1];
    const unsigned int* mask   = (const unsigned int*)d_in[3];
    const float*        ea     = (const float*)d_in[4];
    const float*        Wt0    = (const float*)d_in[5];
    const float*        bt0    = (const float*)d_in[6];
    const float*        Wt1    = (const float*)d_in[7];
    const float*        bt1    = (const float*)d_in[8];
    const float*        Wc0    = (const float*)d_in[9];
    const float*        bc0    = (const float*)d_in[10];
    const float*        Wc1    = (const float*)d_in[11];
    const float*        bc1    = (const float*)d_in[12];
    const float*        gn_w   = (const float*)d_in[13];
    const float*        gn_b   = (const float*)d_in[14];
    const float*        gn_a   = (const float*)d_in[15];
    const float*        Wm1    = (const float*)d_in[16];
    const float*        bm1    = (const float*)d_in[17];
    const float*        Wm2    = (const float*)d_in[18];
    const float*        bm2    = (const float*)d_in[19];
    float*              out    = (float*)d_out;

    int estride = (in_sizes[1] >= 4 * EE) ? 2 : 1;

    cudaFuncSetAttribute(tc_mma_gemm<false>,
                         cudaFuncAttributeMaxDynamicSharedMemorySize, SMEM_DYN);
    cudaFuncSetAttribute(tc_mma_gemm<true>,
                         cudaFuncAttributeMaxDynamicSharedMemorySize, SMEM_DYN);

    init_kernel<<<256, 256>>>();
    prep_weights_kernel<<<64, 256>>>(Wt0, 256, 0);
    prep_weights_kernel<<<64, 256>>>(Wt1, 256, 1);
    prep_weights_kernel<<<128, 256>>>(Wc0, 512, 2);
    prep_weights_kernel<<<128, 256>>>(Wc1, 512, 3);
    edge_mlp_kernel<<<(EE + 255) / 256, 256>>>(ea, ei, estride, Wm1, bm1, Wm2, bm2);
    scan_reduce_kernel<<<SCAN_NB, 1024>>>();
    scan_spine_kernel<<<1, 64>>>();
    scan_final_kernel<<<SCAN_NB, 1024>>>();
    scatter_kernel<<<(EE + 255) / 256, 256>>>(ei, estride);

    dim3 ggrid((NN + 63) / 64, 2);
    // xm = mix(mask, relu(x@Wt1+bt1), relu(x@Wt0+bt0)) -> g_xm
    tc_mma_gemm<false><<<ggrid, 256, SMEM_DYN>>>(x, mask, bt0, bt1, nullptr);

    agg_kernel<<<NN, 256>>>();
    colstats_kernel<<<512, 256>>>();
    normparams_kernel<<<1, 256>>>(gn_w, gn_b, gn_a);

    // out = mix(mask, xc@Wc1+bc1, xc@Wc0+bc0), xc = [norm(agg) | x]
    tc_mma_gemm<true><<<ggrid, 256, SMEM_DYN>>>(x, mask, bc0, bc1, out);
}